// round 7
// baseline (speedup 1.0000x reference)
#include <cuda_runtime.h>
#include <cuda_bf16.h>
#include <math.h>
#include <float.h>

// Problem constants
#define H_     512
#define W_     512
#define HW     (H_ * W_)          // 262144
#define NORG   10
#define SS_    32
#define CH_SHP   1                // channels 1..1024
#define CH_SIZE  1025             // channels 1025,1026
#define CH_HEAT  1027             // channels 1027..1036

// Output layout (flattened tuple, fp32):
//   [0, 2*HW)              size    (2,512,512)
//   [2*HW, 2*HW+20)        centers (10,2) as [px, py]
//   [2*HW+20, ...)         final   (10,512,512)
#define OFF_CENTERS (2 * HW)
#define OFF_FINAL   (2 * HW + 2 * NORG)

#define NSEG 32

__device__ float g_pval[NORG * NSEG];
__device__ int   g_pidx[NORG * NSEG];
__device__ int   g_idx[NORG];
__device__ int   g_r0[NORG], g_c0[NORG], g_sh[NORG], g_sw[NORG];
__device__ float g_shape[NORG * SS_ * SS_];   // 10 x 32 x 32

// ---------------------------------------------------------------------------
// Kernel 1: per-(org, segment) argmax over heat channel. grid = (32, 10).
// First-occurrence semantics: strict > within the ascending per-thread scan,
// (v == best && idx < bestIdx) when merging across threads.
// ---------------------------------------------------------------------------
__global__ void argmax_partial_kernel(const float* __restrict__ feat) {
    const int o   = blockIdx.y;
    const int seg = blockIdx.x;
    const int tid = threadIdx.x;
    const float* h = feat + (size_t)(CH_HEAT + o) * HW;

    const int seg_len = HW / NSEG;       // 8192
    const int start   = seg * seg_len;

    float best = -FLT_MAX;
    int   bidx = 0x7FFFFFFF;
    for (int i = start + tid; i < start + seg_len; i += blockDim.x) {
        float v = h[i];
        if (v > best) { best = v; bidx = i; }
    }

    __shared__ float sv[256];
    __shared__ int   si[256];
    sv[tid] = best; si[tid] = bidx;
    __syncthreads();
    for (int s = 128; s > 0; s >>= 1) {
        if (tid < s) {
            float v2 = sv[tid + s];
            int   i2 = si[tid + s];
            if (v2 > sv[tid] || (v2 == sv[tid] && i2 < si[tid])) {
                sv[tid] = v2; si[tid] = i2;
            }
        }
        __syncthreads();
    }
    if (tid == 0) {
        g_pval[o * NSEG + seg] = sv[0];
        g_pidx[o * NSEG + seg] = si[0];
    }
}

// ---------------------------------------------------------------------------
// Kernel 2: final argmax reduce, centers output, box params, shape gather.
// Single block, 1024 threads.
// ---------------------------------------------------------------------------
__global__ void reduce_gather_kernel(const float* __restrict__ feat,
                                     float* __restrict__ out) {
    const int tid = threadIdx.x;

    if (tid < NORG) {
        float best = -FLT_MAX;
        int   bidx = 0x7FFFFFFF;
        for (int j = 0; j < NSEG; j++) {
            float v = g_pval[tid * NSEG + j];
            int   i = g_pidx[tid * NSEG + j];
            if (v > best || (v == best && i < bidx)) { best = v; bidx = i; }
        }
        g_idx[tid] = bidx;
        int py = bidx / W_;
        int px = bidx % W_;

        // size at the peak: abs(trunc-toward-zero); clamp to >= 1
        int s0 = abs((int)feat[(size_t)CH_SIZE * HW + bidx]);
        int s1 = abs((int)feat[(size_t)(CH_SIZE + 1) * HW + bidx]);
        int sh = s0 > 1 ? s0 : 1;
        int sw = s1 > 1 ? s1 : 1;
        g_sh[tid] = sh;
        g_sw[tid] = sw;
        g_r0[tid] = py - sh / 2;
        g_c0[tid] = px - sw / 2;

        out[OFF_CENTERS + tid * 2 + 0] = (float)px;
        out[OFF_CENTERS + tid * 2 + 1] = (float)py;
    }
    __syncthreads();

    // shape32[o][y][x] = feat[(1 + y*32 + x)*HW + idx[o]]
    for (int i = tid; i < NORG * SS_ * SS_; i += blockDim.x) {
        int o = i >> 10;
        int c = i & 1023;
        g_shape[i] = feat[(size_t)(CH_SHP + c) * HW + g_idx[o]];
    }
}

// ---------------------------------------------------------------------------
// Kernel 3: size channels + final mask. 4 pixels per thread, float4 I/O.
// grid = HW / (256*4) = 256 blocks.
// ---------------------------------------------------------------------------
__global__ void __launch_bounds__(256)
final_kernel(const float* __restrict__ feat, float* __restrict__ out) {
    __shared__ float s_shape[NORG * SS_ * SS_];   // 40 KB
    __shared__ int   s_r0[NORG], s_c0[NORG], s_sh[NORG], s_sw[NORG];
    __shared__ float s_ih[NORG], s_iw[NORG];

    const int tid = threadIdx.x;
    for (int i = tid; i < NORG * SS_ * SS_; i += blockDim.x)
        s_shape[i] = g_shape[i];
    if (tid < NORG) {
        int sh = g_sh[tid], sw = g_sw[tid];
        s_r0[tid] = g_r0[tid];
        s_c0[tid] = g_c0[tid];
        s_sh[tid] = sh;
        s_sw[tid] = sw;
        s_ih[tid] = (float)SS_ / (float)sh;
        s_iw[tid] = (float)SS_ / (float)sw;
    }
    __syncthreads();

    const int p = (blockIdx.x * blockDim.x + tid) * 4;   // base pixel, row-aligned group of 4
    const int r  = p >> 9;
    const int c0 = p & 511;

    // size outputs: abs(trunc toward zero), vectorized
    float4 f0 = *(const float4*)(feat + (size_t)CH_SIZE * HW + p);
    float4 f1 = *(const float4*)(feat + (size_t)(CH_SIZE + 1) * HW + p);
    float4 o0, o1;
    o0.x = fabsf((float)(int)f0.x); o0.y = fabsf((float)(int)f0.y);
    o0.z = fabsf((float)(int)f0.z); o0.w = fabsf((float)(int)f0.w);
    o1.x = fabsf((float)(int)f1.x); o1.y = fabsf((float)(int)f1.y);
    o1.z = fabsf((float)(int)f1.z); o1.w = fabsf((float)(int)f1.w);
    *(float4*)(out + p)      = o0;
    *(float4*)(out + HW + p) = o1;

    float4 salraw = *(const float4*)(feat + p);
    float sal[4];
    sal[0] = 1.0f / (1.0f + expf(-salraw.x));
    sal[1] = 1.0f / (1.0f + expf(-salraw.y));
    sal[2] = 1.0f / (1.0f + expf(-salraw.z));
    sal[3] = 1.0f / (1.0f + expf(-salraw.w));

    float* fo = out + OFF_FINAL;
    #pragma unroll
    for (int o = 0; o < NORG; o++) {
        const int   r0o = s_r0[o], c0o = s_c0[o], sho = s_sh[o], swo = s_sw[o];
        const float iho = s_ih[o], iwo = s_iw[o];
        const float* sp = s_shape + o * (SS_ * SS_);
        const int dr = r - r0o;
        float4 res;
        float* resp = (float*)&res;

        if (dr >= 0 && dr < sho) {
            float sy = ((float)dr + 0.5f) * iho - 0.5f;
            sy = fminf(fmaxf(sy, 0.0f), (float)(SS_ - 1));
            int y0 = (int)floorf(sy);
            int y1 = min(y0 + 1, SS_ - 1);
            float wy = sy - (float)y0;
            #pragma unroll
            for (int k = 0; k < 4; k++) {
                float v = 0.0f;
                int dc = c0 + k - c0o;
                if (dc >= 0 && dc < swo) {
                    float sx = ((float)dc + 0.5f) * iwo - 0.5f;
                    sx = fminf(fmaxf(sx, 0.0f), (float)(SS_ - 1));
                    int x0 = (int)floorf(sx);
                    int x1 = min(x0 + 1, SS_ - 1);
                    float wx = sx - (float)x0;
                    float v00 = sp[y0 * SS_ + x0];
                    float v01 = sp[y0 * SS_ + x1];
                    float v10 = sp[y1 * SS_ + x0];
                    float v11 = sp[y1 * SS_ + x1];
                    float loc = (1.0f - wy) * ((1.0f - wx) * v00 + wx * v01)
                              +          wy * ((1.0f - wx) * v10 + wx * v11);
                    v = sal[k] / (1.0f + expf(-loc));
                }
                resp[k] = v;
            }
        } else {
            res.x = 0.0f; res.y = 0.0f; res.z = 0.0f; res.w = 0.0f;
        }
        *(float4*)(fo + (size_t)o * HW + p) = res;
    }
}

// ---------------------------------------------------------------------------
extern "C" void kernel_launch(void* const* d_in, const int* in_sizes, int n_in,
                              void* d_out, int out_size) {
    const float* feat = (const float*)d_in[0];
    float* out = (float*)d_out;

    dim3 g1(NSEG, NORG);
    argmax_partial_kernel<<<g1, 256>>>(feat);
    reduce_gather_kernel<<<1, 1024>>>(feat, out);
    final_kernel<<<HW / (256 * 4), 256>>>(feat, out);
}

// round 8
// speedup vs baseline: 1.2093x; 1.2093x over previous
#include <cuda_runtime.h>
#include <cuda_bf16.h>
#include <math.h>
#include <float.h>

// Problem constants
#define H_     512
#define W_     512
#define HW     (H_ * W_)          // 262144
#define NORG   10
#define SS_    32
#define CH_SHP   1                // channels 1..1024
#define CH_SIZE  1025             // channels 1025,1026
#define CH_HEAT  1027             // channels 1027..1036

// Output layout (flattened tuple, fp32):
//   [0, 2*HW)              size    (2,512,512)
//   [2*HW, 2*HW+20)        centers (10,2) as [px, py]
//   [2*HW+20, ...)         final   (10,512,512)
#define OFF_CENTERS (2 * HW)
#define OFF_FINAL   (2 * HW + 2 * NORG)

#define NSEG 64                   // segments per org
#define SEG_LEN (HW / NSEG)       // 4096 elements
#define NBLOCKS (NSEG * NORG)     // 640

__device__ float g_pval[NORG * NSEG];
__device__ int   g_pidx[NORG * NSEG];
__device__ int   g_r0[NORG], g_c0[NORG], g_sh[NORG], g_sw[NORG];
__device__ float g_shape[NORG * SS_ * SS_];      // 10 x 32 x 32
__device__ unsigned int g_done;                  // zero-init; self-resetting

// ---------------------------------------------------------------------------
// Kernel 1: segmented argmax (float4, MLP=4) + fused final reduce / param
// compute / shape gather in the last-arriving block.
// First-occurrence semantics: strict > within each thread's ascending scan,
// (v == best && idx < bestIdx) when merging.
// ---------------------------------------------------------------------------
__global__ void __launch_bounds__(256)
argmax_fused_kernel(const float* __restrict__ feat, float* __restrict__ out) {
    const int o   = blockIdx.y;
    const int seg = blockIdx.x;
    const int tid = threadIdx.x;

    // ---- phase 1: scan this block's 4096-element segment with float4 ----
    const float4* h4 = (const float4*)(feat + (size_t)(CH_HEAT + o) * HW
                                       + (size_t)seg * SEG_LEN);
    float best = -FLT_MAX;
    int   bidx = 0x7FFFFFFF;
    #pragma unroll
    for (int j = 0; j < 4; j++) {
        const int q = tid + j * 256;             // ascending per thread
        float4 v = h4[q];
        const int base = seg * SEG_LEN + q * 4;
        if (v.x > best) { best = v.x; bidx = base;     }
        if (v.y > best) { best = v.y; bidx = base + 1; }
        if (v.z > best) { best = v.z; bidx = base + 2; }
        if (v.w > best) { best = v.w; bidx = base + 3; }
    }

    __shared__ float sv[256];
    __shared__ int   si[256];
    sv[tid] = best; si[tid] = bidx;
    __syncthreads();
    for (int s = 128; s > 0; s >>= 1) {
        if (tid < s) {
            float v2 = sv[tid + s];
            int   i2 = si[tid + s];
            if (v2 > sv[tid] || (v2 == sv[tid] && i2 < si[tid])) {
                sv[tid] = v2; si[tid] = i2;
            }
        }
        __syncthreads();
    }
    if (tid == 0) {
        g_pval[o * NSEG + seg] = sv[0];
        g_pidx[o * NSEG + seg] = si[0];
    }

    // ---- phase 2: last block finishes the job ----
    __shared__ int s_last;
    __threadfence();
    if (tid == 0) {
        unsigned int prev = atomicAdd(&g_done, 1u);
        s_last = (prev == NBLOCKS - 1);
        if (s_last) g_done = 0;                  // reset for next graph replay
    }
    __syncthreads();
    if (!s_last) return;
    __threadfence();

    __shared__ int s_idx[NORG];
    const int wid  = tid >> 5;
    const int lane = tid & 31;

    // warp w reduces orgs w, w+8 over their 64 partials
    for (int oo = wid; oo < NORG; oo += 8) {
        float v1 = g_pval[oo * NSEG + lane];
        int   i1 = g_pidx[oo * NSEG + lane];
        float v2 = g_pval[oo * NSEG + lane + 32];
        int   i2 = g_pidx[oo * NSEG + lane + 32];
        if (v2 > v1 || (v2 == v1 && i2 < i1)) { v1 = v2; i1 = i2; }
        #pragma unroll
        for (int s = 16; s > 0; s >>= 1) {
            float vo = __shfl_down_sync(0xFFFFFFFFu, v1, s);
            int   io = __shfl_down_sync(0xFFFFFFFFu, i1, s);
            if (vo > v1 || (vo == v1 && io < i1)) { v1 = vo; i1 = io; }
        }
        if (lane == 0) s_idx[oo] = i1;
    }
    __syncthreads();

    if (tid < NORG) {
        const int bi = s_idx[tid];
        const int py = bi / W_;
        const int px = bi % W_;

        // size at the peak: abs(trunc-toward-zero); clamp to >= 1
        int s0 = abs((int)feat[(size_t)CH_SIZE * HW + bi]);
        int s1 = abs((int)feat[(size_t)(CH_SIZE + 1) * HW + bi]);
        int sh = s0 > 1 ? s0 : 1;
        int sw = s1 > 1 ? s1 : 1;
        g_sh[tid] = sh;
        g_sw[tid] = sw;
        g_r0[tid] = py - sh / 2;
        g_c0[tid] = px - sw / 2;

        out[OFF_CENTERS + tid * 2 + 0] = (float)px;
        out[OFF_CENTERS + tid * 2 + 1] = (float)py;
    }
    __syncthreads();

    // shape gather: shape32[o][c] = feat[(1 + c)*HW + idx[o]]
    // 10240 independent scattered loads across 256 threads (40 each).
    for (int i = tid; i < NORG * SS_ * SS_; i += 256) {
        const int oo = i >> 10;
        const int c  = i & 1023;
        g_shape[i] = feat[(size_t)(CH_SHP + c) * HW + s_idx[oo]];
    }
}

// ---------------------------------------------------------------------------
// Kernel 2: size channels + final mask. 4 pixels per thread, float4 I/O.
// grid = HW / (256*4) = 256 blocks.
// ---------------------------------------------------------------------------
__global__ void __launch_bounds__(256)
final_kernel(const float* __restrict__ feat, float* __restrict__ out) {
    __shared__ float s_shape[NORG * SS_ * SS_];   // 40 KB
    __shared__ int   s_r0[NORG], s_c0[NORG], s_sh[NORG], s_sw[NORG];
    __shared__ float s_ih[NORG], s_iw[NORG];

    const int tid = threadIdx.x;
    {
        const float4* src = (const float4*)g_shape;
        float4* dst = (float4*)s_shape;
        #pragma unroll
        for (int i = 0; i < (NORG * SS_ * SS_) / 4 / 256; i++)
            dst[tid + i * 256] = src[tid + i * 256];
    }
    if (tid < NORG) {
        int sh = g_sh[tid], sw = g_sw[tid];
        s_r0[tid] = g_r0[tid];
        s_c0[tid] = g_c0[tid];
        s_sh[tid] = sh;
        s_sw[tid] = sw;
        s_ih[tid] = (float)SS_ / (float)sh;
        s_iw[tid] = (float)SS_ / (float)sw;
    }
    __syncthreads();

    const int p  = (blockIdx.x * blockDim.x + tid) * 4;  // row-aligned group of 4
    const int r  = p >> 9;
    const int c0 = p & 511;

    // size outputs: abs(trunc toward zero), vectorized
    float4 f0 = *(const float4*)(feat + (size_t)CH_SIZE * HW + p);
    float4 f1 = *(const float4*)(feat + (size_t)(CH_SIZE + 1) * HW + p);
    float4 o0, o1;
    o0.x = fabsf((float)(int)f0.x); o0.y = fabsf((float)(int)f0.y);
    o0.z = fabsf((float)(int)f0.z); o0.w = fabsf((float)(int)f0.w);
    o1.x = fabsf((float)(int)f1.x); o1.y = fabsf((float)(int)f1.y);
    o1.z = fabsf((float)(int)f1.z); o1.w = fabsf((float)(int)f1.w);
    *(float4*)(out + p)      = o0;
    *(float4*)(out + HW + p) = o1;

    float4 salraw = *(const float4*)(feat + p);
    float sal[4];
    sal[0] = 1.0f / (1.0f + expf(-salraw.x));
    sal[1] = 1.0f / (1.0f + expf(-salraw.y));
    sal[2] = 1.0f / (1.0f + expf(-salraw.z));
    sal[3] = 1.0f / (1.0f + expf(-salraw.w));

    float* fo = out + OFF_FINAL;
    #pragma unroll
    for (int o = 0; o < NORG; o++) {
        const int   r0o = s_r0[o], c0o = s_c0[o], sho = s_sh[o], swo = s_sw[o];
        const float iho = s_ih[o], iwo = s_iw[o];
        const float* sp = s_shape + o * (SS_ * SS_);
        const int dr = r - r0o;
        float4 res;
        float* resp = (float*)&res;

        if (dr >= 0 && dr < sho) {
            float sy = ((float)dr + 0.5f) * iho - 0.5f;
            sy = fminf(fmaxf(sy, 0.0f), (float)(SS_ - 1));
            int y0 = (int)floorf(sy);
            int y1 = min(y0 + 1, SS_ - 1);
            float wy = sy - (float)y0;
            #pragma unroll
            for (int k = 0; k < 4; k++) {
                float v = 0.0f;
                int dc = c0 + k - c0o;
                if (dc >= 0 && dc < swo) {
                    float sx = ((float)dc + 0.5f) * iwo - 0.5f;
                    sx = fminf(fmaxf(sx, 0.0f), (float)(SS_ - 1));
                    int x0 = (int)floorf(sx);
                    int x1 = min(x0 + 1, SS_ - 1);
                    float wx = sx - (float)x0;
                    float v00 = sp[y0 * SS_ + x0];
                    float v01 = sp[y0 * SS_ + x1];
                    float v10 = sp[y1 * SS_ + x0];
                    float v11 = sp[y1 * SS_ + x1];
                    float loc = (1.0f - wy) * ((1.0f - wx) * v00 + wx * v01)
                              +          wy * ((1.0f - wx) * v10 + wx * v11);
                    v = sal[k] / (1.0f + expf(-loc));
                }
                resp[k] = v;
            }
        } else {
            res.x = 0.0f; res.y = 0.0f; res.z = 0.0f; res.w = 0.0f;
        }
        *(float4*)(fo + (size_t)o * HW + p) = res;
    }
}

// ---------------------------------------------------------------------------
extern "C" void kernel_launch(void* const* d_in, const int* in_sizes, int n_in,
                              void* d_out, int out_size) {
    const float* feat = (const float*)d_in[0];
    float* out = (float*)d_out;

    dim3 g1(NSEG, NORG);
    argmax_fused_kernel<<<g1, 256>>>(feat, out);
    final_kernel<<<HW / (256 * 4), 256>>>(feat, out);
}